// round 7
// baseline (speedup 1.0000x reference)
#include <cuda_runtime.h>
#include <math.h>
#include <stdint.h>

#define NB 48
#define SS 1024
#define DD 128
#define DKK 64
#define NPROJ 384               // proj CTAs (128 rows each)

// scratch (static device globals: allocation-free per harness rules)
__device__ float g_Q[NB * SS * DKK];   // tf32-rounded projections
__device__ float g_K[NB * SS * DKK];
__device__ float g_Z[NB];
__device__ int   g_cnt[NB];
__device__ int   g_flag[NPROJ];        // proj-block ready flags
// W split into tf32 hi/lo, TRANSPOSED to [n][k] (n: 0..63 Wq, 64..127 Wk)
__device__ uint32_t g_WhT[DD * DD];
__device__ uint32_t g_WlT[DD * DD];

__device__ __forceinline__ uint32_t f2tf32(float v) {
    uint32_t r;
    asm("cvt.rna.tf32.f32 %0, %1;" : "=r"(r) : "f"(v));
    return r;
}

// ---------------------------------------------------------------------------
// Kernel 0: split W into tf32 hi/lo + transpose; zero g_Z/g_cnt/g_flag.
// Runs (and re-runs on every graph replay) before the fused kernel.
// ---------------------------------------------------------------------------
__global__ __launch_bounds__(256) void setup_kernel(
    const float* __restrict__ Wq, const float* __restrict__ Wk)
{
    int idx = blockIdx.x * 256 + threadIdx.x;   // grid 64 -> 16384
    int k = idx >> 7, n = idx & 127;
    float v = (n < 64) ? Wq[k * DKK + n] : Wk[k * DKK + (n - 64)];
    uint32_t hi = f2tf32(v);
    uint32_t lo = f2tf32(v - __uint_as_float(hi));
    g_WhT[n * DD + k] = hi;
    g_WlT[n * DD + k] = lo;
    if (idx < NB) { g_Z[idx] = 0.f; g_cnt[idx] = 0; }
    if (idx < NPROJ) g_flag[idx] = 0;
}

// ---------------------------------------------------------------------------
// FUSED kernel. bid < NPROJ: projection CTA (3xTF32 split, publishes flag).
// bid >= NPROJ: score CTA (waits on its 2 proj-block flags, then validated
// R6 path: cp.async staging -> tf32 mma -> tanh/exp epilogue in regs ->
// per-batch Z protocol -> single normalized write).
// Deadlock-free: proj CTAs occupy the low bids, CTAs are scheduled in bid
// order, so every flag a score CTA waits on is owned by an earlier CTA;
// score CTAs of one batch are contiguous for the Z-spin protocol.
// ---------------------------------------------------------------------------
#define FUSED_SMEM (4 * 128 * 36 * 4)   // proj needs 73728 > score 69632

__device__ __forceinline__ float uval(float x, int qg, int sg) {
    float e2 = __expf(2.f * x);
    float u  = __expf(-__fdividef(20.f, e2 + 1.f));
    return (qg == sg) ? 0.f : u;
}

__global__ __launch_bounds__(256) void fused_kernel(
    const float* __restrict__ A, float* __restrict__ out)
{
    extern __shared__ uint32_t smem[];
    const int tid  = threadIdx.x;
    const int lane = tid & 31, warp = tid >> 5;
    const int g  = lane >> 2;
    const int tr = lane & 3;

    if (blockIdx.x < NPROJ) {
        // =================== PROJECTION PATH ===================
        uint32_t* sAh = smem;                 // [128][36]
        uint32_t* sAl = sAh + 128 * 36;
        uint32_t* sWh = sAl + 128 * 36;       // [n][k] transposed
        uint32_t* sWl = sWh + 128 * 36;

        const int rowbase = blockIdx.x * 128;
        const int mrow = (warp & 3) * 32;
        const int ncol = (warp >> 2) * 64;

        float acc[2][8][4];
#pragma unroll
        for (int mt = 0; mt < 2; mt++)
#pragma unroll
            for (int nt = 0; nt < 8; nt++)
#pragma unroll
                for (int r = 0; r < 4; r++) acc[mt][nt][r] = 0.f;

        for (int k0 = 0; k0 < DD; k0 += 32) {
#pragma unroll
            for (int it = 0; it < 4; it++) {
                int f = tid + 256 * it;
                int m = f >> 3, k4 = (f & 7) * 4;
                float4 v = *(const float4*)(A + (size_t)(rowbase + m) * DD + k0 + k4);
                uint32_t h0 = f2tf32(v.x), h1 = f2tf32(v.y),
                         h2 = f2tf32(v.z), h3 = f2tf32(v.w);
                sAh[m * 36 + k4 + 0] = h0; sAh[m * 36 + k4 + 1] = h1;
                sAh[m * 36 + k4 + 2] = h2; sAh[m * 36 + k4 + 3] = h3;
                sAl[m * 36 + k4 + 0] = f2tf32(v.x - __uint_as_float(h0));
                sAl[m * 36 + k4 + 1] = f2tf32(v.y - __uint_as_float(h1));
                sAl[m * 36 + k4 + 2] = f2tf32(v.z - __uint_as_float(h2));
                sAl[m * 36 + k4 + 3] = f2tf32(v.w - __uint_as_float(h3));
            }
#pragma unroll
            for (int it = 0; it < 4; it++) {
                int f = tid + 256 * it;
                int n = f >> 3, k4 = (f & 7) * 4;
                uint4 h = *(const uint4*)(g_WhT + n * DD + k0 + k4);
                uint4 l = *(const uint4*)(g_WlT + n * DD + k0 + k4);
                sWh[n * 36 + k4 + 0] = h.x; sWh[n * 36 + k4 + 1] = h.y;
                sWh[n * 36 + k4 + 2] = h.z; sWh[n * 36 + k4 + 3] = h.w;
                sWl[n * 36 + k4 + 0] = l.x; sWl[n * 36 + k4 + 1] = l.y;
                sWl[n * 36 + k4 + 2] = l.z; sWl[n * 36 + k4 + 3] = l.w;
            }
            __syncthreads();

#pragma unroll
            for (int kc = 0; kc < 4; kc++) {
                const int kk = kc * 8;
                uint32_t ah[2][4], al[2][4];
#pragma unroll
                for (int mt = 0; mt < 2; mt++) {
                    int r = mrow + mt * 16 + g;
                    ah[mt][0] = sAh[r * 36 + kk + tr];
                    ah[mt][1] = sAh[(r + 8) * 36 + kk + tr];
                    ah[mt][2] = sAh[r * 36 + kk + tr + 4];
                    ah[mt][3] = sAh[(r + 8) * 36 + kk + tr + 4];
                    al[mt][0] = sAl[r * 36 + kk + tr];
                    al[mt][1] = sAl[(r + 8) * 36 + kk + tr];
                    al[mt][2] = sAl[r * 36 + kk + tr + 4];
                    al[mt][3] = sAl[(r + 8) * 36 + kk + tr + 4];
                }
#pragma unroll
                for (int nt = 0; nt < 8; nt++) {
                    int c = ncol + nt * 8 + g;
                    uint32_t bh0 = sWh[c * 36 + kk + tr];
                    uint32_t bh1 = sWh[c * 36 + kk + tr + 4];
                    uint32_t bl0 = sWl[c * 36 + kk + tr];
                    uint32_t bl1 = sWl[c * 36 + kk + tr + 4];
#pragma unroll
                    for (int mt = 0; mt < 2; mt++) {
                        asm volatile(
                            "mma.sync.aligned.m16n8k8.row.col.f32.tf32.tf32.f32 "
                            "{%0,%1,%2,%3}, {%4,%5,%6,%7}, {%8,%9}, {%0,%1,%2,%3};"
                            : "+f"(acc[mt][nt][0]), "+f"(acc[mt][nt][1]),
                              "+f"(acc[mt][nt][2]), "+f"(acc[mt][nt][3])
                            : "r"(ah[mt][0]), "r"(ah[mt][1]), "r"(ah[mt][2]), "r"(ah[mt][3]),
                              "r"(bh0), "r"(bh1));
                        asm volatile(
                            "mma.sync.aligned.m16n8k8.row.col.f32.tf32.tf32.f32 "
                            "{%0,%1,%2,%3}, {%4,%5,%6,%7}, {%8,%9}, {%0,%1,%2,%3};"
                            : "+f"(acc[mt][nt][0]), "+f"(acc[mt][nt][1]),
                              "+f"(acc[mt][nt][2]), "+f"(acc[mt][nt][3])
                            : "r"(ah[mt][0]), "r"(ah[mt][1]), "r"(ah[mt][2]), "r"(ah[mt][3]),
                              "r"(bl0), "r"(bl1));
                        asm volatile(
                            "mma.sync.aligned.m16n8k8.row.col.f32.tf32.tf32.f32 "
                            "{%0,%1,%2,%3}, {%4,%5,%6,%7}, {%8,%9}, {%0,%1,%2,%3};"
                            : "+f"(acc[mt][nt][0]), "+f"(acc[mt][nt][1]),
                              "+f"(acc[mt][nt][2]), "+f"(acc[mt][nt][3])
                            : "r"(al[mt][0]), "r"(al[mt][1]), "r"(al[mt][2]), "r"(al[mt][3]),
                              "r"(bh0), "r"(bh1));
                    }
                }
            }
            __syncthreads();
        }

        // store tf32-ROUNDED outputs, then publish readiness flag
#pragma unroll
        for (int mt = 0; mt < 2; mt++) {
            int m0 = rowbase + mrow + mt * 16 + g;
#pragma unroll
            for (int nt = 0; nt < 8; nt++) {
                int c = ncol + nt * 8 + tr * 2;
                float* dst = (c < 64) ? g_Q : g_K;
                int cc = c & 63;
                *(float2*)(dst + (size_t)m0 * DKK + cc) = make_float2(
                    __uint_as_float(f2tf32(acc[mt][nt][0])),
                    __uint_as_float(f2tf32(acc[mt][nt][1])));
                *(float2*)(dst + (size_t)(m0 + 8) * DKK + cc) = make_float2(
                    __uint_as_float(f2tf32(acc[mt][nt][2])),
                    __uint_as_float(f2tf32(acc[mt][nt][3])));
            }
        }
        __threadfence();            // each thread: stores ordered before flag
        __syncthreads();
        if (tid == 0) atomicExch(&g_flag[blockIdx.x], 1);

    } else {
        // ===================== SCORE PATH =====================
        uint32_t* sQ = smem;                // [128][68]
        uint32_t* sK = smem + 128 * 68;
        __shared__ float swarp[8];
        __shared__ float sinv;

        const int bid2  = blockIdx.x - NPROJ;
        const int bz    = bid2 >> 6;
        const int tile  = bid2 & 63;
        const int qt    = tile >> 3;
        const int st    = tile & 7;
        const int qbase = qt * 128;
        const int sbase = st * 128;

        // wait for the two producing proj blocks
        if (tid == 0) {
            volatile int* vf = g_flag;
            while (!vf[bz * 8 + qt]) { }
            while (!vf[bz * 8 + st]) { }
        }
        __syncthreads();

        const float* Qb = g_Q + (size_t)bz * SS * DKK + (size_t)qbase * DKK;
        const float* Kb = g_K + (size_t)bz * SS * DKK + (size_t)sbase * DKK;

        const int mrow = (warp & 3) * 32;
        const int ncol = (warp >> 2) * 64;

        // stage full 128x64 Q and K tiles via cp.async (pure copy)
#pragma unroll
        for (int it = 0; it < 8; it++) {
            int f = tid + 256 * it;            // 0..2047
            int m = f >> 4, k4 = (f & 15) * 4;
            uint32_t dq = (uint32_t)__cvta_generic_to_shared(&sQ[m * 68 + k4]);
            asm volatile("cp.async.cg.shared.global [%0], [%1], 16;"
                         :: "r"(dq), "l"(Qb + m * DKK + k4));
            uint32_t dk = (uint32_t)__cvta_generic_to_shared(&sK[m * 68 + k4]);
            asm volatile("cp.async.cg.shared.global [%0], [%1], 16;"
                         :: "r"(dk), "l"(Kb + m * DKK + k4));
        }
        asm volatile("cp.async.commit_group;");

        float acc[2][8][4];
#pragma unroll
        for (int mt = 0; mt < 2; mt++)
#pragma unroll
            for (int nt = 0; nt < 8; nt++)
#pragma unroll
                for (int r = 0; r < 4; r++) acc[mt][nt][r] = 0.f;

        asm volatile("cp.async.wait_group 0;");
        __syncthreads();

#pragma unroll
        for (int kc = 0; kc < 8; kc++) {
            const int k0 = kc * 8;
            uint32_t a[2][4];
#pragma unroll
            for (int mt = 0; mt < 2; mt++) {
                int r = mrow + mt * 16 + g;
                a[mt][0] = sQ[r * 68 + k0 + tr];
                a[mt][1] = sQ[(r + 8) * 68 + k0 + tr];
                a[mt][2] = sQ[r * 68 + k0 + tr + 4];
                a[mt][3] = sQ[(r + 8) * 68 + k0 + tr + 4];
            }
#pragma unroll
            for (int nt = 0; nt < 8; nt++) {
                int c = ncol + nt * 8 + g;
                uint32_t b0 = sK[c * 68 + k0 + tr];
                uint32_t b1 = sK[c * 68 + k0 + tr + 4];
#pragma unroll
                for (int mt = 0; mt < 2; mt++) {
                    asm volatile(
                        "mma.sync.aligned.m16n8k8.row.col.f32.tf32.tf32.f32 "
                        "{%0,%1,%2,%3}, {%4,%5,%6,%7}, {%8,%9}, {%0,%1,%2,%3};"
                        : "+f"(acc[mt][nt][0]), "+f"(acc[mt][nt][1]),
                          "+f"(acc[mt][nt][2]), "+f"(acc[mt][nt][3])
                        : "r"(a[mt][0]), "r"(a[mt][1]), "r"(a[mt][2]), "r"(a[mt][3]),
                          "r"(b0), "r"(b1));
                }
            }
        }

        // transform in place (u stays in registers), accumulate local sum
        float local = 0.f;
#pragma unroll
        for (int mt = 0; mt < 2; mt++) {
            int r0 = qbase + mrow + mt * 16 + g;
#pragma unroll
            for (int nt = 0; nt < 8; nt++) {
                int c = sbase + ncol + nt * 8 + tr * 2;
                float u0 = uval(acc[mt][nt][0], r0,     c);
                float u1 = uval(acc[mt][nt][1], r0,     c + 1);
                float u2 = uval(acc[mt][nt][2], r0 + 8, c);
                float u3 = uval(acc[mt][nt][3], r0 + 8, c + 1);
                acc[mt][nt][0] = u0; acc[mt][nt][1] = u1;
                acc[mt][nt][2] = u2; acc[mt][nt][3] = u3;
                local += (u0 + u1) + (u2 + u3);
            }
        }
#pragma unroll
        for (int o = 16; o; o >>= 1)
            local += __shfl_down_sync(0xffffffffu, local, o);
        if (lane == 0) swarp[warp] = local;
        __syncthreads();
        if (tid == 0) {
            float tot = swarp[0];
#pragma unroll
            for (int w = 1; w < 8; w++) tot += swarp[w];
            atomicAdd(&g_Z[bz], tot);
            __threadfence();
            atomicAdd(&g_cnt[bz], 1);
            volatile int* vc = g_cnt;
            while (vc[bz] < 64) { }
            volatile float* vz = g_Z;
            sinv = 1.0f / vz[bz];
        }
        __syncthreads();
        const float inv = sinv;

        // single normalized write
        float* orow = out + ((size_t)bz << 20);
#pragma unroll
        for (int mt = 0; mt < 2; mt++) {
            int r0 = qbase + mrow + mt * 16 + g;
#pragma unroll
            for (int nt = 0; nt < 8; nt++) {
                int c = sbase + ncol + nt * 8 + tr * 2;
                *(float2*)(orow + (size_t)r0 * SS + c) =
                    make_float2(acc[mt][nt][0] * inv, acc[mt][nt][1] * inv);
                *(float2*)(orow + (size_t)(r0 + 8) * SS + c) =
                    make_float2(acc[mt][nt][2] * inv, acc[mt][nt][3] * inv);
            }
        }
    }
}

// ---------------------------------------------------------------------------
extern "C" void kernel_launch(void* const* d_in, const int* in_sizes, int n_in,
                              void* d_out, int out_size)
{
    const float* q  = (const float*)d_in[0];   // query [48,1024,128]
    const float* wq = (const float*)d_in[3];   // W_query [128,64]
    const float* wk = (const float*)d_in[4];   // W_key   [128,64]
    float* out = (float*)d_out;                // [48, 1024*1024] fp32

    cudaFuncSetAttribute(fused_kernel,
                         cudaFuncAttributeMaxDynamicSharedMemorySize, FUSED_SMEM);

    setup_kernel<<<64, 256>>>(wq, wk);
    fused_kernel<<<NPROJ + NB * 64, 256, FUSED_SMEM>>>(q, out);
}

// round 8
// speedup vs baseline: 1.8949x; 1.8949x over previous
#include <cuda_runtime.h>
#include <math.h>
#include <stdint.h>

#define NB 48
#define SS 1024
#define DD 128
#define DKK 64

// scratch (static device globals: allocation-free per harness rules)
__device__ float g_Q[NB * SS * DKK];   // tf32-rounded projections
__device__ float g_K[NB * SS * DKK];
__device__ float g_Z[NB];
__device__ int   g_cnt[NB];
// W split into tf32 hi/lo, TRANSPOSED to [n][k] (n: 0..63 Wq, 64..127 Wk)
__device__ uint32_t g_WhT[DD * DD];
__device__ uint32_t g_WlT[DD * DD];

__device__ __forceinline__ uint32_t f2tf32(float v) {
    uint32_t r;
    asm("cvt.rna.tf32.f32 %0, %1;" : "=r"(r) : "f"(v));
    return r;
}

// ---------------------------------------------------------------------------
// Kernel 0: split W into tf32 hi/lo and transpose to [n][k]; zero g_Z/g_cnt.
// ---------------------------------------------------------------------------
__global__ __launch_bounds__(256) void setup_kernel(
    const float* __restrict__ Wq, const float* __restrict__ Wk)
{
    int idx = blockIdx.x * 256 + threadIdx.x;   // grid 64 -> 16384
    int k = idx >> 7, n = idx & 127;
    float v = (n < 64) ? Wq[k * DKK + n] : Wk[k * DKK + (n - 64)];
    uint32_t hi = f2tf32(v);
    uint32_t lo = f2tf32(v - __uint_as_float(hi));
    g_WhT[n * DD + k] = hi;
    g_WlT[n * DD + k] = lo;
    if (idx < NB) { g_Z[idx] = 0.f; g_cnt[idx] = 0; }
}

// ---------------------------------------------------------------------------
// Kernel 1: fused Q|K projection on tensor cores, 3xTF32 split precision.
// (R6 structure, unchanged; outputs tf32-rounded for score's cp.async copy.)
// ---------------------------------------------------------------------------
#define PROJ_SMEM (4 * 128 * 36 * 4)

__global__ __launch_bounds__(256) void proj_kernel(const float* __restrict__ A)
{
    extern __shared__ uint32_t smem[];
    uint32_t* sAh = smem;                 // [128][36]
    uint32_t* sAl = sAh + 128 * 36;
    uint32_t* sWh = sAl + 128 * 36;       // [n][k] transposed
    uint32_t* sWl = sWh + 128 * 36;

    const int tid  = threadIdx.x;
    const int lane = tid & 31, warp = tid >> 5;
    const int rowbase = blockIdx.x * 128;

    const int mrow = (warp & 3) * 32;
    const int ncol = (warp >> 2) * 64;
    const int g  = lane >> 2;
    const int tr = lane & 3;

    float acc[2][8][4];
#pragma unroll
    for (int mt = 0; mt < 2; mt++)
#pragma unroll
        for (int nt = 0; nt < 8; nt++)
#pragma unroll
            for (int r = 0; r < 4; r++) acc[mt][nt][r] = 0.f;

    for (int k0 = 0; k0 < DD; k0 += 32) {
#pragma unroll
        for (int it = 0; it < 4; it++) {
            int f = tid + 256 * it;
            int m = f >> 3, k4 = (f & 7) * 4;
            float4 v = *(const float4*)(A + (size_t)(rowbase + m) * DD + k0 + k4);
            uint32_t h0 = f2tf32(v.x), h1 = f2tf32(v.y),
                     h2 = f2tf32(v.z), h3 = f2tf32(v.w);
            sAh[m * 36 + k4 + 0] = h0; sAh[m * 36 + k4 + 1] = h1;
            sAh[m * 36 + k4 + 2] = h2; sAh[m * 36 + k4 + 3] = h3;
            sAl[m * 36 + k4 + 0] = f2tf32(v.x - __uint_as_float(h0));
            sAl[m * 36 + k4 + 1] = f2tf32(v.y - __uint_as_float(h1));
            sAl[m * 36 + k4 + 2] = f2tf32(v.z - __uint_as_float(h2));
            sAl[m * 36 + k4 + 3] = f2tf32(v.w - __uint_as_float(h3));
        }
#pragma unroll
        for (int it = 0; it < 4; it++) {
            int f = tid + 256 * it;
            int n = f >> 3, k4 = (f & 7) * 4;
            uint4 h = *(const uint4*)(g_WhT + n * DD + k0 + k4);
            uint4 l = *(const uint4*)(g_WlT + n * DD + k0 + k4);
            sWh[n * 36 + k4 + 0] = h.x; sWh[n * 36 + k4 + 1] = h.y;
            sWh[n * 36 + k4 + 2] = h.z; sWh[n * 36 + k4 + 3] = h.w;
            sWl[n * 36 + k4 + 0] = l.x; sWl[n * 36 + k4 + 1] = l.y;
            sWl[n * 36 + k4 + 2] = l.z; sWl[n * 36 + k4 + 3] = l.w;
        }
        __syncthreads();

#pragma unroll
        for (int kc = 0; kc < 4; kc++) {
            const int kk = kc * 8;
            uint32_t ah[2][4], al[2][4];
#pragma unroll
            for (int mt = 0; mt < 2; mt++) {
                int r = mrow + mt * 16 + g;
                ah[mt][0] = sAh[r * 36 + kk + tr];
                ah[mt][1] = sAh[(r + 8) * 36 + kk + tr];
                ah[mt][2] = sAh[r * 36 + kk + tr + 4];
                ah[mt][3] = sAh[(r + 8) * 36 + kk + tr + 4];
                al[mt][0] = sAl[r * 36 + kk + tr];
                al[mt][1] = sAl[(r + 8) * 36 + kk + tr];
                al[mt][2] = sAl[r * 36 + kk + tr + 4];
                al[mt][3] = sAl[(r + 8) * 36 + kk + tr + 4];
            }
#pragma unroll
            for (int nt = 0; nt < 8; nt++) {
                int c = ncol + nt * 8 + g;
                uint32_t bh0 = sWh[c * 36 + kk + tr];
                uint32_t bh1 = sWh[c * 36 + kk + tr + 4];
                uint32_t bl0 = sWl[c * 36 + kk + tr];
                uint32_t bl1 = sWl[c * 36 + kk + tr + 4];
#pragma unroll
                for (int mt = 0; mt < 2; mt++) {
                    asm volatile(
                        "mma.sync.aligned.m16n8k8.row.col.f32.tf32.tf32.f32 "
                        "{%0,%1,%2,%3}, {%4,%5,%6,%7}, {%8,%9}, {%0,%1,%2,%3};"
                        : "+f"(acc[mt][nt][0]), "+f"(acc[mt][nt][1]),
                          "+f"(acc[mt][nt][2]), "+f"(acc[mt][nt][3])
                        : "r"(ah[mt][0]), "r"(ah[mt][1]), "r"(ah[mt][2]), "r"(ah[mt][3]),
                          "r"(bh0), "r"(bh1));
                    asm volatile(
                        "mma.sync.aligned.m16n8k8.row.col.f32.tf32.tf32.f32 "
                        "{%0,%1,%2,%3}, {%4,%5,%6,%7}, {%8,%9}, {%0,%1,%2,%3};"
                        : "+f"(acc[mt][nt][0]), "+f"(acc[mt][nt][1]),
                          "+f"(acc[mt][nt][2]), "+f"(acc[mt][nt][3])
                        : "r"(ah[mt][0]), "r"(ah[mt][1]), "r"(ah[mt][2]), "r"(ah[mt][3]),
                          "r"(bl0), "r"(bl1));
                    asm volatile(
                        "mma.sync.aligned.m16n8k8.row.col.f32.tf32.tf32.f32 "
                        "{%0,%1,%2,%3}, {%4,%5,%6,%7}, {%8,%9}, {%0,%1,%2,%3};"
                        : "+f"(acc[mt][nt][0]), "+f"(acc[mt][nt][1]),
                          "+f"(acc[mt][nt][2]), "+f"(acc[mt][nt][3])
                        : "r"(al[mt][0]), "r"(al[mt][1]), "r"(al[mt][2]), "r"(al[mt][3]),
                          "r"(bh0), "r"(bh1));
                }
            }
        }
        __syncthreads();
    }

    // store tf32-ROUNDED outputs (score stages them as a raw copy)
#pragma unroll
    for (int mt = 0; mt < 2; mt++) {
        int m0 = rowbase + mrow + mt * 16 + g;
#pragma unroll
        for (int nt = 0; nt < 8; nt++) {
            int c = ncol + nt * 8 + tr * 2;
            float* dst = (c < 64) ? g_Q : g_K;
            int cc = c & 63;
            *(float2*)(dst + (size_t)m0 * DKK + cc) = make_float2(
                __uint_as_float(f2tf32(acc[mt][nt][0])),
                __uint_as_float(f2tf32(acc[mt][nt][1])));
            *(float2*)(dst + (size_t)(m0 + 8) * DKK + cc) = make_float2(
                __uint_as_float(f2tf32(acc[mt][nt][2])),
                __uint_as_float(f2tf32(acc[mt][nt][3])));
        }
    }
}

// ---------------------------------------------------------------------------
// Kernel 2: score tile + self-normalizing epilogue (R6 protocol).
// Epilogue transform now uses only 2 MUFU ops/elem (EX2, RCP); the second
// exp is a software FMA-pipe evaluation with bounded argument v in (-20,0]:
//   u = exp(v),  k = rint(v*log2e), f = v - k*ln2 (|f|<=0.347),
//   e^f by deg-6 Taylor (rel err ~1.7e-7), scale 2^k by exponent bits
//   (127+k in [98,127] -> always normal, no overflow paths).
// Output stores use __stcs (evict-first) so the 201MB write-once stream does
// not evict the Q/K working set from L2.
// ---------------------------------------------------------------------------
#define SCORE_SMEM (2 * 128 * 68 * 4)

__device__ __forceinline__ float uval(float x, int qg, int sg) {
    float e2 = __expf(2.f * x);              // MUFU EX2 (+mul); inf ok
    float rr;
    asm("rcp.approx.f32 %0, %1;" : "=f"(rr) : "f"(e2 + 1.f));  // MUFU RCP
    float v  = -20.f * rr;                   // (-20, 0]
    // software exp(v) on the FMA pipe
    float t  = v * 1.4426950408889634f;      // v*log2e in (-28.86, 0]
    float kf = rintf(t);
    float f  = fmaf(-kf, 0.6931471805599453f, v);   // |f| <= ln2/2
    float p  = 1.3888888888e-3f;                    // 1/720
    p = fmaf(p, f, 8.3333333333e-3f);               // 1/120
    p = fmaf(p, f, 4.1666666667e-2f);               // 1/24
    p = fmaf(p, f, 1.6666666667e-1f);               // 1/6
    p = fmaf(p, f, 0.5f);
    p = fmaf(p, f, 1.0f);
    p = fmaf(p, f, 1.0f);
    int ki = (int)kf;                               // exact (kf integral)
    float scale = __int_as_float((127 + ki) << 23); // 2^k, k in [-29,0]
    float u = p * scale;
    return (qg == sg) ? 0.f : u;
}

__global__ __launch_bounds__(256, 3) void score_kernel(float* __restrict__ out)
{
    extern __shared__ uint32_t ssm[];
    uint32_t* sQ = ssm;                // [128][68]
    uint32_t* sK = ssm + 128 * 68;
    __shared__ float swarp[8];
    __shared__ float sinv;

    const int tid  = threadIdx.x;
    const int lane = tid & 31, warp = tid >> 5;
    const int bz    = blockIdx.x >> 6;
    const int tile  = blockIdx.x & 63;
    const int qbase = (tile >> 3) * 128;
    const int sbase = (tile & 7) * 128;

    const float* Qb = g_Q + (size_t)bz * SS * DKK + (size_t)qbase * DKK;
    const float* Kb = g_K + (size_t)bz * SS * DKK + (size_t)sbase * DKK;

    const int mrow = (warp & 3) * 32;
    const int ncol = (warp >> 2) * 64;
    const int g  = lane >> 2;
    const int tr = lane & 3;

    // stage full 128x64 Q and K tiles via cp.async (pure copy, MLP=16)
#pragma unroll
    for (int it = 0; it < 8; it++) {
        int f = tid + 256 * it;            // 0..2047
        int m = f >> 4, k4 = (f & 15) * 4;
        uint32_t dq = (uint32_t)__cvta_generic_to_shared(&sQ[m * 68 + k4]);
        asm volatile("cp.async.cg.shared.global [%0], [%1], 16;"
                     :: "r"(dq), "l"(Qb + m * DKK + k4));
        uint32_t dk = (uint32_t)__cvta_generic_to_shared(&sK[m * 68 + k4]);
        asm volatile("cp.async.cg.shared.global [%0], [%1], 16;"
                     :: "r"(dk), "l"(Kb + m * DKK + k4));
    }
    asm volatile("cp.async.commit_group;");

    float acc[2][8][4];
#pragma unroll
    for (int mt = 0; mt < 2; mt++)
#pragma unroll
        for (int nt = 0; nt < 8; nt++)
#pragma unroll
            for (int r = 0; r < 4; r++) acc[mt][nt][r] = 0.f;

    asm volatile("cp.async.wait_group 0;");
    __syncthreads();

#pragma unroll
    for (int kc = 0; kc < 8; kc++) {
        const int k0 = kc * 8;
        uint32_t a[2][4];
#pragma unroll
        for (int mt = 0; mt < 2; mt++) {
            int r = mrow + mt * 16 + g;
            a[mt][0] = sQ[r * 68 + k0 + tr];
            a[mt][1] = sQ[(r + 8) * 68 + k0 + tr];
            a[mt][2] = sQ[r * 68 + k0 + tr + 4];
            a[mt][3] = sQ[(r + 8) * 68 + k0 + tr + 4];
        }
#pragma unroll
        for (int nt = 0; nt < 8; nt++) {
            int c = ncol + nt * 8 + g;
            uint32_t b0 = sK[c * 68 + k0 + tr];
            uint32_t b1 = sK[c * 68 + k0 + tr + 4];
#pragma unroll
            for (int mt = 0; mt < 2; mt++) {
                asm volatile(
                    "mma.sync.aligned.m16n8k8.row.col.f32.tf32.tf32.f32 "
                    "{%0,%1,%2,%3}, {%4,%5,%6,%7}, {%8,%9}, {%0,%1,%2,%3};"
                    : "+f"(acc[mt][nt][0]), "+f"(acc[mt][nt][1]),
                      "+f"(acc[mt][nt][2]), "+f"(acc[mt][nt][3])
                    : "r"(a[mt][0]), "r"(a[mt][1]), "r"(a[mt][2]), "r"(a[mt][3]),
                      "r"(b0), "r"(b1));
            }
        }
    }

    // transform in place (u stays in registers), accumulate local sum
    float local = 0.f;
#pragma unroll
    for (int mt = 0; mt < 2; mt++) {
        int r0 = qbase + mrow + mt * 16 + g;
#pragma unroll
        for (int nt = 0; nt < 8; nt++) {
            int c = sbase + ncol + nt * 8 + tr * 2;
            float u0 = uval(acc[mt][nt][0], r0,     c);
            float u1 = uval(acc[mt][nt][1], r0,     c + 1);
            float u2 = uval(acc[mt][nt][2], r0 + 8, c);
            float u3 = uval(acc[mt][nt][3], r0 + 8, c + 1);
            acc[mt][nt][0] = u0; acc[mt][nt][1] = u1;
            acc[mt][nt][2] = u2; acc[mt][nt][3] = u3;
            local += (u0 + u1) + (u2 + u3);
        }
    }
    // block reduce -> one atomicAdd + arrival count; spin until batch done
#pragma unroll
    for (int o = 16; o; o >>= 1)
        local += __shfl_down_sync(0xffffffffu, local, o);
    if (lane == 0) swarp[warp] = local;
    __syncthreads();
    if (tid == 0) {
        float tot = swarp[0];
#pragma unroll
        for (int w = 1; w < 8; w++) tot += swarp[w];
        atomicAdd(&g_Z[bz], tot);
        __threadfence();
        atomicAdd(&g_cnt[bz], 1);
        volatile int* vc = g_cnt;
        while (vc[bz] < 64) { }
        volatile float* vz = g_Z;
        sinv = 1.0f / vz[bz];
    }
    __syncthreads();
    const float inv = sinv;

    // single normalized write (streaming: keep Q/K resident in L2)
    float* orow = out + ((size_t)bz << 20);
#pragma unroll
    for (int mt = 0; mt < 2; mt++) {
        int r0 = qbase + mrow + mt * 16 + g;
#pragma unroll
        for (int nt = 0; nt < 8; nt++) {
            int c = sbase + ncol + nt * 8 + tr * 2;
            __stcs((float2*)(orow + (size_t)r0 * SS + c),
                   make_float2(acc[mt][nt][0] * inv, acc[mt][nt][1] * inv));
            __stcs((float2*)(orow + (size_t)(r0 + 8) * SS + c),
                   make_float2(acc[mt][nt][2] * inv, acc[mt][nt][3] * inv));
        }
    }
}

// ---------------------------------------------------------------------------
extern "C" void kernel_launch(void* const* d_in, const int* in_sizes, int n_in,
                              void* d_out, int out_size)
{
    const float* q  = (const float*)d_in[0];   // query [48,1024,128]
    const float* wq = (const float*)d_in[3];   // W_query [128,64]
    const float* wk = (const float*)d_in[4];   // W_key   [128,64]
    float* out = (float*)d_out;                // [48, 1024*1024] fp32

    cudaFuncSetAttribute(proj_kernel,
                         cudaFuncAttributeMaxDynamicSharedMemorySize, PROJ_SMEM);
    cudaFuncSetAttribute(score_kernel,
                         cudaFuncAttributeMaxDynamicSharedMemorySize, SCORE_SMEM);

    setup_kernel<<<64, 256>>>(wq, wk);
    proj_kernel<<<384, 256, PROJ_SMEM>>>(q);
    score_kernel<<<3072, 256, SCORE_SMEM>>>(out);
}

// round 9
// speedup vs baseline: 2.2682x; 1.1970x over previous
#include <cuda_runtime.h>
#include <math.h>
#include <stdint.h>

#define NB 48
#define SS 1024
#define DD 128
#define DKK 64

// scratch (static device globals: allocation-free per harness rules)
__device__ float g_Q[NB * SS * DKK];   // tf32-rounded projections
__device__ float g_K[NB * SS * DKK];
__device__ float g_Z[NB];
__device__ int   g_cnt[NB];
// W split into tf32 hi/lo, TRANSPOSED to [n][k] (n: 0..63 Wq, 64..127 Wk)
__device__ uint32_t g_WhT[DD * DD];
__device__ uint32_t g_WlT[DD * DD];

__device__ __forceinline__ uint32_t f2tf32(float v) {
    uint32_t r;
    asm("cvt.rna.tf32.f32 %0, %1;" : "=r"(r) : "f"(v));
    return r;
}

// ---------------------------------------------------------------------------
// Kernel 0: split W into tf32 hi/lo and transpose to [n][k]; zero g_Z/g_cnt.
// ---------------------------------------------------------------------------
__global__ __launch_bounds__(256) void setup_kernel(
    const float* __restrict__ Wq, const float* __restrict__ Wk)
{
    int idx = blockIdx.x * 256 + threadIdx.x;   // grid 64 -> 16384
    int k = idx >> 7, n = idx & 127;
    float v = (n < 64) ? Wq[k * DKK + n] : Wk[k * DKK + (n - 64)];
    uint32_t hi = f2tf32(v);
    uint32_t lo = f2tf32(v - __uint_as_float(hi));
    g_WhT[n * DD + k] = hi;
    g_WlT[n * DD + k] = lo;
    if (idx < NB) { g_Z[idx] = 0.f; g_cnt[idx] = 0; }
}

// ---------------------------------------------------------------------------
// Kernel 1: fused Q|K projection, 2-term tf32: C = Ah*Wh + Ah*Wl.
// W's hi/lo split is exact (Wh+Wl = W), so the only approximation is
// dropping (A-Ah)*W ~ 1.2e-4 rms — below the score-side tf32 noise.
// vs R6: 1/3 fewer MMAs, no A-lo staging/fragments, smem 73.7->55.3 KB.
// Outputs tf32-rounded so score stages them as a pure cp.async copy.
// ---------------------------------------------------------------------------
#define PROJ_SMEM (3 * 128 * 36 * 4)

__global__ __launch_bounds__(256) void proj_kernel(const float* __restrict__ A)
{
    extern __shared__ uint32_t smem[];
    uint32_t* sAh = smem;                 // [128][36]
    uint32_t* sWh = sAh + 128 * 36;       // [n][k] transposed
    uint32_t* sWl = sWh + 128 * 36;

    const int tid  = threadIdx.x;
    const int lane = tid & 31, warp = tid >> 5;
    const int rowbase = blockIdx.x * 128;

    const int mrow = (warp & 3) * 32;
    const int ncol = (warp >> 2) * 64;
    const int g  = lane >> 2;
    const int tr = lane & 3;

    float acc[2][8][4];
#pragma unroll
    for (int mt = 0; mt < 2; mt++)
#pragma unroll
        for (int nt = 0; nt < 8; nt++)
#pragma unroll
            for (int r = 0; r < 4; r++) acc[mt][nt][r] = 0.f;

    for (int k0 = 0; k0 < DD; k0 += 32) {
        // stage A chunk 128x32, tf32 hi only, vectorized STS.128
        // (row stride 36*4=144B = 9*16B -> uint4-aligned)
#pragma unroll
        for (int it = 0; it < 4; it++) {
            int f = tid + 256 * it;
            int m = f >> 3, k4 = (f & 7) * 4;
            float4 v = *(const float4*)(A + (size_t)(rowbase + m) * DD + k0 + k4);
            uint4 h = make_uint4(f2tf32(v.x), f2tf32(v.y),
                                 f2tf32(v.z), f2tf32(v.w));
            *(uint4*)&sAh[m * 36 + k4] = h;
        }
#pragma unroll
        for (int it = 0; it < 4; it++) {
            int f = tid + 256 * it;
            int n = f >> 3, k4 = (f & 7) * 4;
            *(uint4*)&sWh[n * 36 + k4] = *(const uint4*)(g_WhT + n * DD + k0 + k4);
            *(uint4*)&sWl[n * 36 + k4] = *(const uint4*)(g_WlT + n * DD + k0 + k4);
        }
        __syncthreads();

#pragma unroll
        for (int kc = 0; kc < 4; kc++) {
            const int kk = kc * 8;
            uint32_t ah[2][4];
#pragma unroll
            for (int mt = 0; mt < 2; mt++) {
                int r = mrow + mt * 16 + g;
                ah[mt][0] = sAh[r * 36 + kk + tr];
                ah[mt][1] = sAh[(r + 8) * 36 + kk + tr];
                ah[mt][2] = sAh[r * 36 + kk + tr + 4];
                ah[mt][3] = sAh[(r + 8) * 36 + kk + tr + 4];
            }
#pragma unroll
            for (int nt = 0; nt < 8; nt++) {
                int c = ncol + nt * 8 + g;
                uint32_t bh0 = sWh[c * 36 + kk + tr];
                uint32_t bh1 = sWh[c * 36 + kk + tr + 4];
                uint32_t bl0 = sWl[c * 36 + kk + tr];
                uint32_t bl1 = sWl[c * 36 + kk + tr + 4];
#pragma unroll
                for (int mt = 0; mt < 2; mt++) {
                    asm volatile(
                        "mma.sync.aligned.m16n8k8.row.col.f32.tf32.tf32.f32 "
                        "{%0,%1,%2,%3}, {%4,%5,%6,%7}, {%8,%9}, {%0,%1,%2,%3};"
                        : "+f"(acc[mt][nt][0]), "+f"(acc[mt][nt][1]),
                          "+f"(acc[mt][nt][2]), "+f"(acc[mt][nt][3])
                        : "r"(ah[mt][0]), "r"(ah[mt][1]), "r"(ah[mt][2]), "r"(ah[mt][3]),
                          "r"(bh0), "r"(bh1));
                    asm volatile(
                        "mma.sync.aligned.m16n8k8.row.col.f32.tf32.tf32.f32 "
                        "{%0,%1,%2,%3}, {%4,%5,%6,%7}, {%8,%9}, {%0,%1,%2,%3};"
                        : "+f"(acc[mt][nt][0]), "+f"(acc[mt][nt][1]),
                          "+f"(acc[mt][nt][2]), "+f"(acc[mt][nt][3])
                        : "r"(ah[mt][0]), "r"(ah[mt][1]), "r"(ah[mt][2]), "r"(ah[mt][3]),
                          "r"(bl0), "r"(bl1));
                }
            }
        }
        __syncthreads();
    }

    // store tf32-ROUNDED outputs (score stages them as a raw copy)
#pragma unroll
    for (int mt = 0; mt < 2; mt++) {
        int m0 = rowbase + mrow + mt * 16 + g;
#pragma unroll
        for (int nt = 0; nt < 8; nt++) {
            int c = ncol + nt * 8 + tr * 2;
            float* dst = (c < 64) ? g_Q : g_K;
            int cc = c & 63;
            *(float2*)(dst + (size_t)m0 * DKK + cc) = make_float2(
                __uint_as_float(f2tf32(acc[mt][nt][0])),
                __uint_as_float(f2tf32(acc[mt][nt][1])));
            *(float2*)(dst + (size_t)(m0 + 8) * DKK + cc) = make_float2(
                __uint_as_float(f2tf32(acc[mt][nt][2])),
                __uint_as_float(f2tf32(acc[mt][nt][3])));
        }
    }
}

// ---------------------------------------------------------------------------
// Kernel 2: score tile + self-normalizing epilogue (R6-exact protocol and
// epilogue arithmetic — 3 MUFU path, plain stores). One change: tiles off
// the batch diagonal (56 of 64) skip the per-element q==s compare/select.
// ---------------------------------------------------------------------------
#define SCORE_SMEM (2 * 128 * 68 * 4)

__device__ __forceinline__ float uexp(float x) {
    float e2 = __expf(2.f * x);
    return __expf(-__fdividef(20.f, e2 + 1.f));
}

__global__ __launch_bounds__(256, 3) void score_kernel(float* __restrict__ out)
{
    extern __shared__ uint32_t ssm[];
    uint32_t* sQ = ssm;                // [128][68]
    uint32_t* sK = ssm + 128 * 68;
    __shared__ float swarp[8];
    __shared__ float sinv;

    const int tid  = threadIdx.x;
    const int lane = tid & 31, warp = tid >> 5;
    const int bz    = blockIdx.x >> 6;
    const int tile  = blockIdx.x & 63;
    const int qbase = (tile >> 3) * 128;
    const int sbase = (tile & 7) * 128;

    const float* Qb = g_Q + (size_t)bz * SS * DKK + (size_t)qbase * DKK;
    const float* Kb = g_K + (size_t)bz * SS * DKK + (size_t)sbase * DKK;

    const int mrow = (warp & 3) * 32;
    const int ncol = (warp >> 2) * 64;
    const int g  = lane >> 2;
    const int tr = lane & 3;

    // stage full 128x64 Q and K tiles via cp.async (pure copy, MLP=16)
#pragma unroll
    for (int it = 0; it < 8; it++) {
        int f = tid + 256 * it;            // 0..2047
        int m = f >> 4, k4 = (f & 15) * 4;
        uint32_t dq = (uint32_t)__cvta_generic_to_shared(&sQ[m * 68 + k4]);
        asm volatile("cp.async.cg.shared.global [%0], [%1], 16;"
                     :: "r"(dq), "l"(Qb + m * DKK + k4));
        uint32_t dk = (uint32_t)__cvta_generic_to_shared(&sK[m * 68 + k4]);
        asm volatile("cp.async.cg.shared.global [%0], [%1], 16;"
                     :: "r"(dk), "l"(Kb + m * DKK + k4));
    }
    asm volatile("cp.async.commit_group;");

    float acc[2][8][4];
#pragma unroll
    for (int mt = 0; mt < 2; mt++)
#pragma unroll
        for (int nt = 0; nt < 8; nt++)
#pragma unroll
            for (int r = 0; r < 4; r++) acc[mt][nt][r] = 0.f;

    asm volatile("cp.async.wait_group 0;");
    __syncthreads();

#pragma unroll
    for (int kc = 0; kc < 8; kc++) {
        const int k0 = kc * 8;
        uint32_t a[2][4];
#pragma unroll
        for (int mt = 0; mt < 2; mt++) {
            int r = mrow + mt * 16 + g;
            a[mt][0] = sQ[r * 68 + k0 + tr];
            a[mt][1] = sQ[(r + 8) * 68 + k0 + tr];
            a[mt][2] = sQ[r * 68 + k0 + tr + 4];
            a[mt][3] = sQ[(r + 8) * 68 + k0 + tr + 4];
        }
#pragma unroll
        for (int nt = 0; nt < 8; nt++) {
            int c = ncol + nt * 8 + g;
            uint32_t b0 = sK[c * 68 + k0 + tr];
            uint32_t b1 = sK[c * 68 + k0 + tr + 4];
#pragma unroll
            for (int mt = 0; mt < 2; mt++) {
                asm volatile(
                    "mma.sync.aligned.m16n8k8.row.col.f32.tf32.tf32.f32 "
                    "{%0,%1,%2,%3}, {%4,%5,%6,%7}, {%8,%9}, {%0,%1,%2,%3};"
                    : "+f"(acc[mt][nt][0]), "+f"(acc[mt][nt][1]),
                      "+f"(acc[mt][nt][2]), "+f"(acc[mt][nt][3])
                    : "r"(a[mt][0]), "r"(a[mt][1]), "r"(a[mt][2]), "r"(a[mt][3]),
                      "r"(b0), "r"(b1));
            }
        }
    }

    // transform in place (u stays in registers), accumulate local sum.
    // Diagonal tiles (8/64) take the branch with the q==s select; the other
    // 56/64 skip the per-element compare entirely (uniform per CTA).
    float local = 0.f;
    if (qbase == sbase) {
#pragma unroll
        for (int mt = 0; mt < 2; mt++) {
            int r0 = mrow + mt * 16 + g;            // local row == local col space
#pragma unroll
            for (int nt = 0; nt < 8; nt++) {
                int c = ncol + nt * 8 + tr * 2;
                float u0 = uexp(acc[mt][nt][0]); if (r0     == c    ) u0 = 0.f;
                float u1 = uexp(acc[mt][nt][1]); if (r0     == c + 1) u1 = 0.f;
                float u2 = uexp(acc[mt][nt][2]); if (r0 + 8 == c    ) u2 = 0.f;
                float u3 = uexp(acc[mt][nt][3]); if (r0 + 8 == c + 1) u3 = 0.f;
                acc[mt][nt][0] = u0; acc[mt][nt][1] = u1;
                acc[mt][nt][2] = u2; acc[mt][nt][3] = u3;
                local += (u0 + u1) + (u2 + u3);
            }
        }
    } else {
#pragma unroll
        for (int mt = 0; mt < 2; mt++)
#pragma unroll
            for (int nt = 0; nt < 8; nt++) {
                float u0 = uexp(acc[mt][nt][0]);
                float u1 = uexp(acc[mt][nt][1]);
                float u2 = uexp(acc[mt][nt][2]);
                float u3 = uexp(acc[mt][nt][3]);
                acc[mt][nt][0] = u0; acc[mt][nt][1] = u1;
                acc[mt][nt][2] = u2; acc[mt][nt][3] = u3;
                local += (u0 + u1) + (u2 + u3);
            }
    }
    // block reduce -> one atomicAdd + arrival count; spin until batch done
#pragma unroll
    for (int o = 16; o; o >>= 1)
        local += __shfl_down_sync(0xffffffffu, local, o);
    if (lane == 0) swarp[warp] = local;
    __syncthreads();
    if (tid == 0) {
        float tot = swarp[0];
#pragma unroll
        for (int w = 1; w < 8; w++) tot += swarp[w];
        atomicAdd(&g_Z[bz], tot);
        __threadfence();
        atomicAdd(&g_cnt[bz], 1);
        volatile int* vc = g_cnt;
        while (vc[bz] < 64) { }
        volatile float* vz = g_Z;
        sinv = 1.0f / vz[bz];
    }
    __syncthreads();
    const float inv = sinv;

    // single normalized write
    float* orow = out + ((size_t)bz << 20);
#pragma unroll
    for (int mt = 0; mt < 2; mt++) {
        int r0 = qbase + mrow + mt * 16 + g;
#pragma unroll
        for (int nt = 0; nt < 8; nt++) {
            int c = sbase + ncol + nt * 8 + tr * 2;
            *(float2*)(orow + (size_t)r0 * SS + c) =
                make_float2(acc[mt][nt][0] * inv, acc[mt][nt][1] * inv);
            *(float2*)(orow + (size_t)(r0 + 8) * SS + c) =
                make_float2(acc[mt][nt][2] * inv, acc[mt][nt][3] * inv);
        }
    }
}

// ---------------------------------------------------------------------------
extern "C" void kernel_launch(void* const* d_in, const int* in_sizes, int n_in,
                              void* d_out, int out_size)
{
    const float* q  = (const float*)d_in[0];   // query [48,1024,128]
    const float* wq = (const float*)d_in[3];   // W_query [128,64]
    const float* wk = (const float*)d_in[4];   // W_key   [128,64]
    float* out = (float*)d_out;                // [48, 1024*1024] fp32

    cudaFuncSetAttribute(proj_kernel,
                         cudaFuncAttributeMaxDynamicSharedMemorySize, PROJ_SMEM);
    cudaFuncSetAttribute(score_kernel,
                         cudaFuncAttributeMaxDynamicSharedMemorySize, SCORE_SMEM);

    setup_kernel<<<64, 256>>>(wq, wk);
    proj_kernel<<<384, 256, PROJ_SMEM>>>(q);
    score_kernel<<<3072, 256, SCORE_SMEM>>>(out);
}